// round 1
// baseline (speedup 1.0000x reference)
#include <cuda_runtime.h>
#include <cuda_bf16.h>
#include <math.h>

// ---------------- Problem constants ----------------
#define BATCH 2
#define SEQ 2048
#define NTOK (BATCH*SEQ)          // 4096
#define DMODEL 1024
#define DFF 2048
#define NHEADS 16
#define NKVHEADS 4
#define HD 64
#define KVDIM (NKVHEADS*HD)       // 256
#define NEXP 8
#define TOPK 2
#define NSLOT (NTOK*TOPK)         // 8192
#define NSLOT_PAD 9216            // 8192 + 8*128 padding capacity

// ---------------- Device scratch (static, no cudaMalloc) ----------------
__device__ float g_xn[NTOK*DMODEL];          // rmsnorm output (reused for both norms)
__device__ float g_q[NTOK*DMODEL];
__device__ float g_k[NTOK*KVDIM];
__device__ float g_v[NTOK*KVDIM];
__device__ float g_attn[NTOK*DMODEL];
__device__ float g_x1[NTOK*DMODEL];          // residual after attention
__device__ float g_Hg[NSLOT_PAD*DFF];
__device__ float g_Hu[NSLOT_PAD*DFF];
__device__ float g_Y[NSLOT_PAD*DMODEL];
__device__ int   g_perm[NSLOT_PAD];
__device__ float g_prob[NSLOT_PAD];
__device__ int   g_posOf[NTOK*TOPK];
__device__ int   g_topk_e[NTOK*TOPK];
__device__ float g_topk_p[NTOK*TOPK];
__device__ float g_probs_all[NTOK*NEXP];
__device__ int   g_cnt[NEXP];
__device__ int   g_off[NEXP+1];
__device__ int   g_cur[NEXP];
__device__ float g_Psum[NEXP];

// ---------------- init ----------------
__global__ void init_kernel() {
    int i = blockIdx.x*256 + threadIdx.x;
    if (i < NSLOT_PAD) g_perm[i] = -1;
    if (i < NEXP) { g_cnt[i] = 0; g_Psum[i] = 0.f; }
}

// ---------------- RMSNorm ----------------
__global__ void rmsnorm_kernel(const float* __restrict__ X, const float* __restrict__ W,
                               float* __restrict__ Y) {
    int t = blockIdx.x;
    const float4* xr = (const float4*)(X + (long long)t*DMODEL);
    float4* yr = (float4*)(Y + (long long)t*DMODEL);
    int tid = threadIdx.x;  // 256 threads, 4 floats each
    float4 xv = xr[tid];
    float ss = xv.x*xv.x + xv.y*xv.y + xv.z*xv.z + xv.w*xv.w;
    #pragma unroll
    for (int off=16; off; off>>=1) ss += __shfl_xor_sync(0xffffffffu, ss, off);
    __shared__ float red[8];
    if ((tid & 31) == 0) red[tid>>5] = ss;
    __syncthreads();
    if (tid < 8) {
        float v = red[tid];
        #pragma unroll
        for (int off=4; off; off>>=1) v += __shfl_xor_sync(0xffu, v, off);
        if (tid == 0) red[0] = v;
    }
    __syncthreads();
    float r = rsqrtf(red[0]/(float)DMODEL + 1e-6f);
    float4 wv = ((const float4*)W)[tid];
    yr[tid] = make_float4(xv.x*r*wv.x, xv.y*r*wv.y, xv.z*r*wv.z, xv.w*r*wv.w);
}

// ---------------- Generic tiled SGEMM: C[M,N](+res) = A[M,K] @ B[N,K]^T ----------------
// perm != null: A row gather (perm<0 -> zero row).
// off  != null: per-expert tiles; B base += e*strideB; exit if tile beyond off[8].
#define BM 128
#define BN 128
#define BK 16
__global__ __launch_bounds__(256) void sgemm_kernel(
    const float* __restrict__ A, const float* __restrict__ B, float* __restrict__ C,
    int M, int N, int K,
    const int* __restrict__ perm, const float* __restrict__ residual,
    const int* __restrict__ off, long long strideB)
{
    __shared__ float As[BK][BM+4];
    __shared__ float Bs[BK][BN+4];
    int row0 = blockIdx.y * BM;
    int col0 = blockIdx.x * BN;
    if (off) {
        if (row0 >= off[NEXP]) return;
        int e = 0;
        #pragma unroll
        for (int i=1; i<NEXP; i++) if (row0 >= off[i]) e = i;
        B += (long long)e * strideB;
    }
    int tid = threadIdx.x;
    int tx = tid & 15, ty = tid >> 4;
    float acc[8][8];
    #pragma unroll
    for (int i=0;i<8;i++)
        #pragma unroll
        for (int j=0;j<8;j++) acc[i][j] = 0.f;

    int lr  = tid >> 2;           // 0..63
    int lc4 = (tid & 3) * 4;      // 0,4,8,12

    const float* aptr[2]; bool avalid[2];
    #pragma unroll
    for (int p=0;p<2;p++) {
        int grow = row0 + lr + p*64;
        int arow = grow;
        bool val = (grow < M);
        if (perm != nullptr && val) { arow = perm[grow]; if (arow < 0) val = false; }
        avalid[p] = val;
        aptr[p] = A + (long long)(val ? arow : 0) * K;
    }
    const float* bptr[2];
    #pragma unroll
    for (int p=0;p<2;p++) bptr[p] = B + (long long)(col0 + lr + p*64) * K;

    for (int k0=0; k0<K; k0+=BK) {
        #pragma unroll
        for (int p=0;p<2;p++) {
            float4 a = avalid[p] ? *(const float4*)(aptr[p] + k0 + lc4)
                                 : make_float4(0.f,0.f,0.f,0.f);
            int r = lr + p*64;
            As[lc4+0][r]=a.x; As[lc4+1][r]=a.y; As[lc4+2][r]=a.z; As[lc4+3][r]=a.w;
        }
        #pragma unroll
        for (int p=0;p<2;p++) {
            float4 b = *(const float4*)(bptr[p] + k0 + lc4);
            int r = lr + p*64;
            Bs[lc4+0][r]=b.x; Bs[lc4+1][r]=b.y; Bs[lc4+2][r]=b.z; Bs[lc4+3][r]=b.w;
        }
        __syncthreads();
        #pragma unroll
        for (int kk=0; kk<BK; kk++) {
            float af[8], bf[8];
            #pragma unroll
            for (int i=0;i<8;i++) af[i] = As[kk][ty*8+i];
            #pragma unroll
            for (int j=0;j<8;j++) bf[j] = Bs[kk][tx*8+j];
            #pragma unroll
            for (int i=0;i<8;i++)
                #pragma unroll
                for (int j=0;j<8;j++)
                    acc[i][j] += af[i]*bf[j];
        }
        __syncthreads();
    }
    #pragma unroll
    for (int i=0;i<8;i++) {
        int r = row0 + ty*8 + i;
        if (r >= M) continue;
        float* crow = C + (long long)r * N + col0 + tx*8;
        if (residual != nullptr) {
            const float* rrow = residual + (long long)r * N + col0 + tx*8;
            #pragma unroll
            for (int j=0;j<8;j++) crow[j] = acc[i][j] + rrow[j];
        } else {
            #pragma unroll
            for (int j=0;j<8;j++) crow[j] = acc[i][j];
        }
    }
}

// ---------------- RoPE (interleaved pairs, freq idx = (2m)%32) ----------------
__global__ void rope_kernel(float* __restrict__ X, int ld) {
    int token = blockIdx.x;
    int s = token & (SEQ-1);
    int tid = threadIdx.x;
    int h = tid >> 5, m = tid & 31;
    int f = (2*m) & 31;
    float freq = powf(10000.f, -(float)f/32.f);
    float ang = (float)s * freq;
    float c = cosf(ang), sn = sinf(ang);
    float* p = X + (long long)token*ld + h*HD + 2*m;
    float x1 = p[0], x2 = p[1];
    p[0] = x1*c - x2*sn;
    p[1] = x1*sn + x2*c;
}

// ---------------- Flash attention (causal, GQA) ----------------
__global__ __launch_bounds__(64) void attn_kernel(
    const float* __restrict__ Q, const float* __restrict__ K,
    const float* __restrict__ V, float* __restrict__ O)
{
    __shared__ float Ks[64][64];
    __shared__ float Vs[64][64];
    int tid = threadIdx.x;              // 0..63
    int q0 = blockIdx.x * 64;
    int h  = blockIdx.y;
    int b  = blockIdx.z;
    int kvh = h >> 2;
    int qi = q0 + tid;
    long long t = (long long)b*SEQ + qi;

    float q[HD], o[HD];
    const float4* qp = (const float4*)(Q + t*DMODEL + h*HD);
    #pragma unroll
    for (int i=0;i<16;i++) {
        float4 f = qp[i];
        q[4*i]=f.x*0.125f; q[4*i+1]=f.y*0.125f; q[4*i+2]=f.z*0.125f; q[4*i+3]=f.w*0.125f;
    }
    #pragma unroll
    for (int d=0; d<HD; d++) o[d] = 0.f;
    float m = -1e30f, l = 0.f;

    int ntiles = q0/64 + 1;
    for (int kt=0; kt<ntiles; kt++) {
        for (int idx=tid; idx<64*16; idx+=64) {
            int r = idx >> 4, c4 = idx & 15;
            long long base = ((long long)(b*SEQ + kt*64 + r))*KVDIM + kvh*HD + c4*4;
            *(float4*)&Ks[r][c4*4] = *(const float4*)(K + base);
            *(float4*)&Vs[r][c4*4] = *(const float4*)(V + base);
        }
        __syncthreads();
        int jend = min(64, qi - kt*64 + 1);
        for (int j=0; j<jend; j++) {
            float s0=0.f,s1=0.f,s2=0.f,s3=0.f;
            const float4* kr = (const float4*)&Ks[j][0];
            #pragma unroll
            for (int i=0;i<16;i++) {
                float4 kv4 = kr[i];
                s0 += q[4*i]*kv4.x; s1 += q[4*i+1]*kv4.y;
                s2 += q[4*i+2]*kv4.z; s3 += q[4*i+3]*kv4.w;
            }
            float s = (s0+s1)+(s2+s3);
            if (s > m) {
                float corr = __expf(m - s);
                l *= corr;
                #pragma unroll
                for (int d=0; d<HD; d++) o[d] *= corr;
                m = s;
            }
            float p = __expf(s - m);
            l += p;
            const float4* vr = (const float4*)&Vs[j][0];
            #pragma unroll
            for (int i=0;i<16;i++) {
                float4 vv = vr[i];
                o[4*i]   += p*vv.x; o[4*i+1] += p*vv.y;
                o[4*i+2] += p*vv.z; o[4*i+3] += p*vv.w;
            }
        }
        __syncthreads();
    }
    float inv = 1.f / l;
    float4* op = (float4*)(O + t*DMODEL + h*HD);
    #pragma unroll
    for (int i=0;i<16;i++)
        op[i] = make_float4(o[4*i]*inv, o[4*i+1]*inv, o[4*i+2]*inv, o[4*i+3]*inv);
}

// ---------------- Router: logits, softmax, top-2, counts ----------------
__global__ void router_kernel(const float* __restrict__ XN, const float* __restrict__ RW) {
    __shared__ float sw[NEXP*DMODEL];
    int tid = threadIdx.x;  // 256
    for (int i=tid; i<NEXP*DMODEL/4; i+=256)
        ((float4*)sw)[i] = ((const float4*)RW)[i];
    __syncthreads();
    int warp = tid >> 5, lane = tid & 31;
    int token = blockIdx.x*8 + warp;
    const float* xr = XN + (long long)token*DMODEL;
    float acc[NEXP];
    #pragma unroll
    for (int e=0;e<NEXP;e++) acc[e]=0.f;
    for (int d=lane; d<DMODEL; d+=32) {
        float xv = xr[d];
        #pragma unroll
        for (int e=0;e<NEXP;e++) acc[e] += xv * sw[e*DMODEL + d];
    }
    #pragma unroll
    for (int e=0;e<NEXP;e++)
        #pragma unroll
        for (int off=16; off; off>>=1) acc[e] += __shfl_xor_sync(0xffffffffu, acc[e], off);
    if (lane == 0) {
        float mx = acc[0];
        #pragma unroll
        for (int e=1;e<NEXP;e++) mx = fmaxf(mx, acc[e]);
        float pe[NEXP], sum = 0.f;
        #pragma unroll
        for (int e=0;e<NEXP;e++) { pe[e] = expf(acc[e]-mx); sum += pe[e]; }
        float inv = 1.f/sum;
        #pragma unroll
        for (int e=0;e<NEXP;e++) { pe[e] *= inv; g_probs_all[token*NEXP+e] = pe[e]; }
        int e1 = 0; float p1 = pe[0];
        #pragma unroll
        for (int e=1;e<NEXP;e++) if (pe[e] > p1) { p1 = pe[e]; e1 = e; }
        int e2 = -1; float p2 = -1.f;
        #pragma unroll
        for (int e=0;e<NEXP;e++) if (e != e1 && pe[e] > p2) { p2 = pe[e]; e2 = e; }
        float rn = 1.f/(p1+p2);
        g_topk_e[token*2]   = e1;  g_topk_e[token*2+1] = e2;
        g_topk_p[token*2]   = p1*rn; g_topk_p[token*2+1] = p2*rn;
        atomicAdd(&g_cnt[e1], 1);
        atomicAdd(&g_cnt[e2], 1);
    }
}

// Deterministic fixed-order reduction of probs per expert
__global__ void psum_kernel() {
    int e = blockIdx.x;       // 8 blocks
    int tid = threadIdx.x;    // 256
    float acc = 0.f;
    for (int t=tid; t<NTOK; t+=256) acc += g_probs_all[t*NEXP + e];
    #pragma unroll
    for (int off=16; off; off>>=1) acc += __shfl_xor_sync(0xffffffffu, acc, off);
    __shared__ float red[8];
    if ((tid & 31) == 0) red[tid>>5] = acc;
    __syncthreads();
    if (tid < 8) {
        float v = red[tid];
        #pragma unroll
        for (int off=4; off; off>>=1) v += __shfl_xor_sync(0xffu, v, off);
        if (tid == 0) g_Psum[e] = v;
    }
}

// Offsets (padded to 128), cursors, aux_loss + tokens_per_expert tail outputs
__global__ void finalize_kernel(float* __restrict__ out, int out_size) {
    if (threadIdx.x == 0 && blockIdx.x == 0) {
        int total = 0;
        for (int e=0; e<NEXP; e++) {
            g_off[e] = total;
            g_cur[e] = total;
            total += ((g_cnt[e] + 127)/128)*128;
        }
        g_off[NEXP] = total;
        float aux = 0.f;
        for (int e=0; e<NEXP; e++) {
            float f = (float)g_cnt[e] / (float)NSLOT;
            float P = g_Psum[e] / (float)NTOK;
            aux += f * P;
        }
        out[out_size-9] = (float)NEXP * aux;
        for (int e=0; e<NEXP; e++) out[out_size-8+e] = (float)g_cnt[e];
    }
}

__global__ void assign_kernel() {
    int token = blockIdx.x*256 + threadIdx.x;
    if (token >= NTOK) return;
    #pragma unroll
    for (int kk=0; kk<TOPK; kk++) {
        int e = g_topk_e[token*2+kk];
        int pos = atomicAdd(&g_cur[e], 1);
        g_perm[pos] = token;
        g_prob[pos] = g_topk_p[token*2+kk];
        g_posOf[token*2+kk] = pos;
    }
}

// h = silu(g) * u, in place into g_Hg (float4)
__global__ void silumul_kernel() {
    long long i = (long long)blockIdx.x*blockDim.x + threadIdx.x;
    const long long n4 = (long long)NSLOT_PAD*DFF/4;
    if (i < n4) {
        float4 g = ((float4*)g_Hg)[i];
        float4 u = ((float4*)g_Hu)[i];
        g.x = g.x / (1.f + __expf(-g.x)) * u.x;
        g.y = g.y / (1.f + __expf(-g.y)) * u.y;
        g.z = g.z / (1.f + __expf(-g.z)) * u.z;
        g.w = g.w / (1.f + __expf(-g.w)) * u.w;
        ((float4*)g_Hg)[i] = g;
    }
}

// out[t] = x1[t] + p1*Y[pos1] + p2*Y[pos2]
__global__ void combine_kernel(float* __restrict__ out) {
    int t = blockIdx.x;
    int tid = threadIdx.x;  // 256
    int p1i = g_posOf[t*2], p2i = g_posOf[t*2+1];
    float p1 = g_prob[p1i], p2 = g_prob[p2i];
    float4 a  = ((const float4*)(g_x1 + (long long)t*DMODEL))[tid];
    float4 y1 = ((const float4*)(g_Y  + (long long)p1i*DMODEL))[tid];
    float4 y2 = ((const float4*)(g_Y  + (long long)p2i*DMODEL))[tid];
    ((float4*)(out + (long long)t*DMODEL))[tid] = make_float4(
        a.x + p1*y1.x + p2*y2.x,
        a.y + p1*y1.y + p2*y2.y,
        a.z + p1*y1.z + p2*y2.z,
        a.w + p1*y1.w + p2*y2.w);
}

// ---------------- Host launch ----------------
extern "C" void kernel_launch(void* const* d_in, const int* in_sizes, int n_in,
                              void* d_out, int out_size) {
    const float* x        = (const float*)d_in[0];
    const float* wq       = (const float*)d_in[1];
    const float* wk       = (const float*)d_in[2];
    const float* wv       = (const float*)d_in[3];
    const float* wo       = (const float*)d_in[4];
    const float* attn_nw  = (const float*)d_in[5];
    const float* ffn_nw   = (const float*)d_in[6];
    const float* router_w = (const float*)d_in[7];
    const float* Wg       = (const float*)d_in[8];
    const float* Wu       = (const float*)d_in[9];
    const float* Wd       = (const float*)d_in[10];
    float* out = (float*)d_out;

    float *p_xn, *p_q, *p_k, *p_v, *p_attn, *p_x1, *p_Hg, *p_Hu, *p_Y;
    int *p_perm, *p_off;
    cudaGetSymbolAddress((void**)&p_xn,  g_xn);
    cudaGetSymbolAddress((void**)&p_q,   g_q);
    cudaGetSymbolAddress((void**)&p_k,   g_k);
    cudaGetSymbolAddress((void**)&p_v,   g_v);
    cudaGetSymbolAddress((void**)&p_attn,g_attn);
    cudaGetSymbolAddress((void**)&p_x1,  g_x1);
    cudaGetSymbolAddress((void**)&p_Hg,  g_Hg);
    cudaGetSymbolAddress((void**)&p_Hu,  g_Hu);
    cudaGetSymbolAddress((void**)&p_Y,   g_Y);
    cudaGetSymbolAddress((void**)&p_perm,g_perm);
    cudaGetSymbolAddress((void**)&p_off, g_off);

    // 0. init (perm=-1, counters=0)
    init_kernel<<<(NSLOT_PAD+255)/256, 256>>>();

    // 1. rmsnorm(x) -> xn
    rmsnorm_kernel<<<NTOK, 256>>>(x, attn_nw, p_xn);

    // 2. q/k/v projections
    sgemm_kernel<<<dim3(DMODEL/BN, NTOK/BM), 256>>>(p_xn, wq, p_q, NTOK, DMODEL, DMODEL,
                                                    nullptr, nullptr, nullptr, 0);
    sgemm_kernel<<<dim3(KVDIM/BN, NTOK/BM), 256>>>(p_xn, wk, p_k, NTOK, KVDIM, DMODEL,
                                                   nullptr, nullptr, nullptr, 0);
    sgemm_kernel<<<dim3(KVDIM/BN, NTOK/BM), 256>>>(p_xn, wv, p_v, NTOK, KVDIM, DMODEL,
                                                   nullptr, nullptr, nullptr, 0);

    // 3. RoPE
    rope_kernel<<<NTOK, NHEADS*32>>>(p_q, DMODEL);
    rope_kernel<<<NTOK, NKVHEADS*32>>>(p_k, KVDIM);

    // 4. attention
    attn_kernel<<<dim3(SEQ/64, NHEADS, BATCH), 64>>>(p_q, p_k, p_v, p_attn);

    // 5. o-projection + residual -> x1
    sgemm_kernel<<<dim3(DMODEL/BN, NTOK/BM), 256>>>(p_attn, wo, p_x1, NTOK, DMODEL, DMODEL,
                                                    nullptr, x, nullptr, 0);

    // 6. rmsnorm(x1) -> xn
    rmsnorm_kernel<<<NTOK, 256>>>(p_x1, ffn_nw, p_xn);

    // 7. routing
    router_kernel<<<NTOK/8, 256>>>(p_xn, router_w);
    psum_kernel<<<NEXP, 256>>>();
    finalize_kernel<<<1, 32>>>(out, out_size);
    assign_kernel<<<NTOK/256, 256>>>();

    // 8. grouped FFN: g/u GEMMs with token gather, per-expert weights
    sgemm_kernel<<<dim3(DFF/BN, NSLOT_PAD/BM), 256>>>(p_xn, Wg, p_Hg, NSLOT_PAD, DFF, DMODEL,
                                                      p_perm, nullptr, p_off,
                                                      (long long)DFF*DMODEL);
    sgemm_kernel<<<dim3(DFF/BN, NSLOT_PAD/BM), 256>>>(p_xn, Wu, p_Hu, NSLOT_PAD, DFF, DMODEL,
                                                      p_perm, nullptr, p_off,
                                                      (long long)DFF*DMODEL);
    // 9. h = silu(g)*u
    silumul_kernel<<<(int)(((long long)NSLOT_PAD*DFF/4 + 255)/256), 256>>>();

    // 10. down GEMM
    sgemm_kernel<<<dim3(DMODEL/BN, NSLOT_PAD/BM), 256>>>(p_Hg, Wd, p_Y, NSLOT_PAD, DMODEL, DFF,
                                                         nullptr, nullptr, p_off,
                                                         (long long)DMODEL*DFF);

    // 11. combine: out = x1 + p1*Y1 + p2*Y2
    combine_kernel<<<NTOK, 256>>>(out);
}